// round 13
// baseline (speedup 1.0000x reference)
#include <cuda_runtime.h>

// C4ByteTransformer R12: zero inter-CTA communication.
// Softmax factorizes as EA[a]*EB[b]*EC[c]/Z. The carry chain needs only
// {Tlow, Thigh, S255} per step, each computable in O(256) without the conv:
//   Tall = sum(EA)*sum(EB);  Tlow = sum_j EA[255-j]*prefix(EB)[j];
//   S255 = sum_j EA[255-j]*EB[j];  Thigh = Tall - Tlow.
// Every CTA redundantly computes all 4 steps' exps + triples + carry chain,
// and runs the full 256x256 convolution ONLY for its own step's outputs.
// Classic launch (no cluster) -> no CLC dispatch overhead.

__global__ __launch_bounds__(1024, 1)
void c4_indep_kernel(const float* __restrict__ a_emb,
                     const float* __restrict__ b_emb,
                     float* __restrict__ out) {
    __shared__ __align__(16) float EA_all[1024];   // [s][a] for all 4 steps
    __shared__ __align__(16) float EB_all[1024];   // [s][b] for all 4 steps
    __shared__ __align__(16) float EBp[1024];      // own-step EB at [255+b], 0-pad
    __shared__ __align__(16) float Spart[8 * 512];
    __shared__ __align__(16) float S[513];         // S[0]=0, S[1+m]=S_step[m]
    __shared__ float chunkTot[32];                 // per-warp 32-chunk sums of EB
    __shared__ float Trip[4][4];                   // [s]{Tlow, S255, SumA, SumB}
    __shared__ float ECiZ[3];                      // own step {EC0, EC1, iZ}

    const int tid  = threadIdx.x;
    const int step = blockIdx.x;
    const int lane = tid & 31;
    const int w    = tid >> 5;                     // warp 0..31

    // ---- Phase A: all 4 steps' exponentials. thread = (s=tid>>8, e=tid&255)
    const float av = a_emb[tid];
    const float bv = b_emb[tid];
    float ebp = 0.f;                               // own-step padded EB (dup exp
    if (tid >= 255 && tid < 511)                   // avoids zero-init race)
        ebp = __expf(10.f * b_emb[(step << 8) + tid - 255]);
    const float eav = __expf(10.f * av);
    const float ebv = __expf(10.f * bv);
    EA_all[tid] = eav;
    EB_all[tid] = ebv;
    EBp[tid]    = ebp;
    if (tid < 16) ((float*)Trip)[tid] = 0.f;
    if (tid == 0) S[0] = 0.f;
    __syncthreads();                               // #1

    // ---- Phase B: convolution partials for OWN step ----
    // thread = (as, mg): outputs m in [4*mg, 4*mg+3], a in [32*as, 32*as+31].
    // EBp index for (m, a) = 255 + m - a; 8-float register window slides by 4.
    const float* EA = &EA_all[step << 8];
    {
        const int as    = tid >> 7;
        const int mg    = tid & 127;
        const int m0    = mg << 2;
        const int abase = as << 5;
        const int J0    = 252 + m0 - abase;        // in [28, 760], 16B aligned
        float4 lo = *(const float4*)&EBp[J0];
        float4 hi = *(const float4*)&EBp[J0 + 4];
        float s0 = 0.f, s1 = 0.f, s2 = 0.f, s3 = 0.f;
        #pragma unroll
        for (int k = 0; k < 8; ++k) {
            float4 ea = *(const float4*)&EA[abase + 4 * k];
            s0 = fmaf(ea.x, lo.w, s0); s0 = fmaf(ea.y, lo.z, s0);
            s0 = fmaf(ea.z, lo.y, s0); s0 = fmaf(ea.w, lo.x, s0);
            s1 = fmaf(ea.x, hi.x, s1); s1 = fmaf(ea.y, lo.w, s1);
            s1 = fmaf(ea.z, lo.z, s1); s1 = fmaf(ea.w, lo.y, s1);
            s2 = fmaf(ea.x, hi.y, s2); s2 = fmaf(ea.y, hi.x, s2);
            s2 = fmaf(ea.z, lo.w, s2); s2 = fmaf(ea.w, lo.z, s2);
            s3 = fmaf(ea.x, hi.z, s3); s3 = fmaf(ea.y, hi.y, s3);
            s3 = fmaf(ea.z, hi.x, s3); s3 = fmaf(ea.w, lo.w, s3);
            if (k < 7) { hi = lo; lo = *(const float4*)&EBp[J0 - 4 * (k + 1)]; }
        }
        *(float4*)&Spart[as * 512 + m0] = make_float4(s0, s1, s2, s3);
    }

    // ---- Phase S1: warp-level inclusive scan of EB (thread = (s, j)) ----
    float pb = ebv;
    #pragma unroll
    for (int off = 1; off < 32; off <<= 1) {
        float n = __shfl_up_sync(0xffffffffu, pb, off);
        if (lane >= off) pb += n;
    }
    if (lane == 31) chunkTot[w] = pb;
    __syncthreads();                               // #2 (covers Spart + chunkTot)

    // ---- Phase S2: finish prefix, compute triple contributions, reduce ----
    {
        const int c = w & 7, sbase = (w >> 3) << 3;
        float offsum = 0.f;
        for (int cc = 0; cc < c; ++cc) offsum += chunkTot[sbase + cc];
        pb += offsum;                              // pb = PB_s[j], inclusive
    }
    {
        const int sj = tid >> 8, j = tid & 255;
        const float ea_rev = EA_all[(sj << 8) + 255 - j];
        float cl = ea_rev * pb;                    // -> Tlow
        float cs = ea_rev * ebv;                   // -> S255
        float ca = eav;                            // -> SumA
        float cb = ebv;                            // -> SumB
        #pragma unroll
        for (int off = 16; off > 0; off >>= 1) {
            cl += __shfl_down_sync(0xffffffffu, cl, off);
            cs += __shfl_down_sync(0xffffffffu, cs, off);
            ca += __shfl_down_sync(0xffffffffu, ca, off);
            cb += __shfl_down_sync(0xffffffffu, cb, off);
        }
        if (lane == 0) {
            atomicAdd(&Trip[sj][0], cl);
            atomicAdd(&Trip[sj][1], cs);
            atomicAdd(&Trip[sj][2], ca);
            atomicAdd(&Trip[sj][3], cb);
        }
    }

    // ---- Phase C: combine conv partials into S ----
    if (tid < 512) {
        float s = 0.f;
        #pragma unroll
        for (int p = 0; p < 8; ++p) s += Spart[p * 512 + tid];
        S[1 + tid] = s;                            // S[m=tid]; S[511]=0 naturally
    }
    __syncthreads();                               // #3

    // ---- Phase E: carry chain (every CTA, redundantly) ----
    if (tid == 0) {
        float c0 = 1.f, c1 = 0.f;                  // carry0 = (1, 0)
        #pragma unroll
        for (int s = 0; s < 4; ++s) {
            const float Tlow  = Trip[s][0];
            const float S255  = Trip[s][1];
            const float Tall  = Trip[s][2] * Trip[s][3];
            const float Thigh = Tall - Tlow;
            const float E0 = __expf(10.f * c0), E1 = __expf(10.f * c1);
            const float iZ = 1.0f / ((E0 + E1) * Tall);
            if (s == step) { ECiZ[0] = E0; ECiZ[1] = E1; ECiZ[2] = iZ; }
            c0 = (E0 * Tlow  + E1 * (Tlow  - S255)) * iZ;
            c1 = (E0 * Thigh + E1 * (Thigh + S255)) * iZ;
        }
    }
    __syncthreads();                               // #4

    // ---- Phase F: outputs for own step ----
    if (tid < 256) {
        const float E0 = ECiZ[0], E1 = ECiZ[1], iZ = ECiZ[2];
        // c=0: bins m=d and m=d+256 ; c=1: bins m=d-1 and m=d+255
        float num = E0 * (S[1 + tid] + S[257 + tid])
                  + E1 * (S[tid]     + S[256 + tid]);
        out[(step << 8) + tid] = num * iZ;
    }
}

extern "C" void kernel_launch(void* const* d_in, const int* in_sizes, int n_in,
                              void* d_out, int out_size) {
    const float* a_emb = (const float*)d_in[0];   // [4, 256]
    const float* b_emb = (const float*)d_in[1];   // [4, 256]
    float* out = (float*)d_out;                   // [4, 256]
    (void)in_sizes; (void)n_in; (void)out_size;
    c4_indep_kernel<<<4, 1024>>>(a_emb, b_emb, out);
}